// round 1
// baseline (speedup 1.0000x reference)
#include <cuda_runtime.h>
#include <cuda_fp16.h>
#include <cstdint>

// CapsuleLayer dynamic routing, 3 rounds.
// x: [512, 1152, 8] fp32   W: [10, 1152, 8, 16] fp32
// out: [10, 512, 16] fp32
//
// Block = (n, 4 batches). Phase 1: priors p[b][r][16] computed once into fp16
// smem (rows padded to 20 halves to reduce LDS bank conflicts). Phase 2:
// routing entirely from smem:
//   v0 = squash(mean_r p_r)
//   round k (k=1,2): a_r = p_r . w   (w = v0, then v0+v1)
//     softmax over r, S = sum e_r p_r, v = squash(S/Z)
//   output v2.

#define NCAPS 10
#define NB    512
#define NR    1152
#define CI    8
#define CO    16
#define BT    4
#define NTHREADS 384
#define GROUPS (NB / BT)          // 128
#define TPB   96                  // threads per batch (3 warps)
#define JN    6                   // r-stripes in (j,o) phases: TPB/CO
#define RPT   (NR / NTHREADS)     // 3
#define KPT   (NR / TPB)          // 12
#define PSTR  20                  // padded halves per prior row (16 data + 4 pad)

// shared memory layout (bytes)
#define P_BYTES    (BT * NR * PSTR * 2)    // 184320  fp16 priors
#define E_OFF      P_BYTES
#define E_BYTES    (BT * NR * 4)           // 18432   exp(a-m) per r
#define RED_OFF    (E_OFF + E_BYTES)
#define RED_BYTES  (BT * JN * CO * 4)      // 1536    (j,o) partial sums
#define WRED_OFF   (RED_OFF + RED_BYTES)
#define WRED_BYTES (BT * 4 * 4)            // 64      per-warp scalar reduce
#define VOUT_OFF   (WRED_OFF + WRED_BYTES)
#define VOUT_BYTES (BT * CO * 4)           // 256     squash scratch / result
#define VDOT_OFF   (VOUT_OFF + VOUT_BYTES)
#define VDOT_BYTES (BT * CO * 4)           // 256     dot vector (v0, then v0+v1)
#define SMEM_TOTAL (VDOT_OFF + VDOT_BYTES) // 204864

struct __align__(8) H4 { __half2 a, b; };

__global__ void __launch_bounds__(NTHREADS, 1)
caps_kernel(const float* __restrict__ x,
            const float* __restrict__ W,
            float* __restrict__ out) {
    extern __shared__ char smem[];
    __half* p   = (__half*)smem;
    float* ebuf = (float*)(smem + E_OFF);
    float* red  = (float*)(smem + RED_OFF);
    float* wred = (float*)(smem + WRED_OFF);
    float* vout = (float*)(smem + VOUT_OFF);
    float* vdot = (float*)(smem + VDOT_OFF);

    const int n  = blockIdx.y;
    const int b0 = blockIdx.x * BT;
    const int t  = threadIdx.x;

    // ================= Phase 1: priors GEMM (x @ W per r) =================
    #pragma unroll
    for (int rr = 0; rr < RPT; ++rr) {
        const int r = t + rr * NTHREADS;
        // x[b0..b0+3][r][0..7] into registers
        float xv[BT][CI];
        #pragma unroll
        for (int b = 0; b < BT; ++b) {
            const float4* xp = (const float4*)(x + ((size_t)(b0 + b) * NR + r) * CI);
            const float4 x0 = xp[0], x1 = xp[1];
            xv[b][0]=x0.x; xv[b][1]=x0.y; xv[b][2]=x0.z; xv[b][3]=x0.w;
            xv[b][4]=x1.x; xv[b][5]=x1.y; xv[b][6]=x1.z; xv[b][7]=x1.w;
        }
        const float* wr = W + ((size_t)n * NR + r) * (CI * CO);
        #pragma unroll
        for (int oh = 0; oh < 2; ++oh) {
            float acc[BT][8];
            #pragma unroll
            for (int b = 0; b < BT; ++b)
                #pragma unroll
                for (int o = 0; o < 8; ++o) acc[b][o] = 0.f;
            #pragma unroll
            for (int i = 0; i < CI; ++i) {
                const float4 w0 = *(const float4*)(wr + i * CO + oh * 8);
                const float4 w1 = *(const float4*)(wr + i * CO + oh * 8 + 4);
                #pragma unroll
                for (int b = 0; b < BT; ++b) {
                    const float xx = xv[b][i];
                    acc[b][0] += xx * w0.x; acc[b][1] += xx * w0.y;
                    acc[b][2] += xx * w0.z; acc[b][3] += xx * w0.w;
                    acc[b][4] += xx * w1.x; acc[b][5] += xx * w1.y;
                    acc[b][6] += xx * w1.z; acc[b][7] += xx * w1.w;
                }
            }
            #pragma unroll
            for (int b = 0; b < BT; ++b) {
                H4 h0, h1;
                h0.a = __floats2half2_rn(acc[b][0], acc[b][1]);
                h0.b = __floats2half2_rn(acc[b][2], acc[b][3]);
                h1.a = __floats2half2_rn(acc[b][4], acc[b][5]);
                h1.b = __floats2half2_rn(acc[b][6], acc[b][7]);
                H4* dst = (H4*)(p + (size_t)(b * NR + r) * PSTR + oh * 8);
                dst[0] = h0;
                dst[1] = h1;
            }
        }
    }
    __syncthreads();

    // ================= Phase 2: routing (all from smem) =================
    const int b  = t / TPB;        // 0..3
    const int tb = t % TPB;        // 0..95 (warp-aligned: 3 warps per b)
    const int jj = tb / CO;        // 0..5
    const int oo = tb % CO;        // 0..15
    const int wl = tb >> 5;        // warp within b: 0..2

    // ---- S0 = sum_r p_r ; v0 = squash(S0 / NR) ----
    {
        float s = 0.f;
        #pragma unroll 4
        for (int r = jj; r < NR; r += JN)
            s += __half2float(p[(size_t)(b * NR + r) * PSTR + oo]);
        red[(b * JN + jj) * CO + oo] = s;
    }
    __syncthreads();
    if (tb < CO) {
        float s = 0.f;
        #pragma unroll
        for (int j = 0; j < JN; ++j) s += red[(b * JN + j) * CO + tb];
        vout[b * CO + tb] = s * (1.0f / NR);
    }
    __syncthreads();
    if (tb < CO) {
        float snorm = 0.f;
        #pragma unroll
        for (int o = 0; o < CO; ++o) { const float v = vout[b * CO + o]; snorm += v * v; }
        const float coef = snorm / ((1.f + snorm) * sqrtf(snorm));
        vdot[b * CO + tb] = vout[b * CO + tb] * coef;   // v0
    }
    __syncthreads();

    // ---- rounds 1 and 2: softmax(p.w) weighted sum + squash ----
    for (int round = 0; round < 2; ++round) {
        float vd[CO];
        #pragma unroll
        for (int o = 0; o < CO; ++o) vd[o] = vdot[b * CO + o];

        // a_r = p_r . w, track local max
        float aval[KPT];
        float mloc = -1e30f;
        #pragma unroll
        for (int k = 0; k < KPT; ++k) {
            const int r = tb + k * TPB;
            const __half* pr = p + (size_t)(b * NR + r) * PSTR;
            float a = 0.f;
            #pragma unroll
            for (int q = 0; q < 4; ++q) {
                const H4 u = *(const H4*)(pr + q * 4);
                const float2 f0 = __half22float2(u.a);
                const float2 f1 = __half22float2(u.b);
                a += f0.x * vd[q*4+0] + f0.y * vd[q*4+1]
                   + f1.x * vd[q*4+2] + f1.y * vd[q*4+3];
            }
            aval[k] = a;
            mloc = fmaxf(mloc, a);
        }
        // block max per b (warp shfl + 3-warp smem combine)
        #pragma unroll
        for (int off = 16; off; off >>= 1)
            mloc = fmaxf(mloc, __shfl_xor_sync(0xffffffffu, mloc, off));
        if ((tb & 31) == 0) wred[b * 4 + wl] = mloc;
        __syncthreads();
        const float m = fmaxf(fmaxf(wred[b*4+0], wred[b*4+1]), wred[b*4+2]);
        __syncthreads();

        // e_r and Z
        float zloc = 0.f;
        #pragma unroll
        for (int k = 0; k < KPT; ++k) {
            const int r = tb + k * TPB;
            const float e = __expf(aval[k] - m);
            ebuf[b * NR + r] = e;
            zloc += e;
        }
        #pragma unroll
        for (int off = 16; off; off >>= 1)
            zloc += __shfl_xor_sync(0xffffffffu, zloc, off);
        if ((tb & 31) == 0) wred[b * 4 + wl] = zloc;
        __syncthreads();
        const float Z = wred[b*4+0] + wred[b*4+1] + wred[b*4+2];

        // S = sum_r e_r * p_r  via (j,o) mapping
        {
            float s = 0.f;
            #pragma unroll 4
            for (int r = jj; r < NR; r += JN)
                s += ebuf[b * NR + r] *
                     __half2float(p[(size_t)(b * NR + r) * PSTR + oo]);
            red[(b * JN + jj) * CO + oo] = s;
        }
        __syncthreads();
        if (tb < CO) {
            float s = 0.f;
            #pragma unroll
            for (int j = 0; j < JN; ++j) s += red[(b * JN + j) * CO + tb];
            vout[b * CO + tb] = s / Z;
        }
        __syncthreads();
        if (tb < CO) {
            float snorm = 0.f;
            #pragma unroll
            for (int o = 0; o < CO; ++o) { const float v = vout[b * CO + o]; snorm += v * v; }
            const float coef = snorm / ((1.f + snorm) * sqrtf(snorm));
            const float v = vout[b * CO + tb] * coef;
            if (round == 0)
                vdot[b * CO + tb] += v;                 // w = v0 + v1 for round 2
            else
                out[((size_t)n * NB + (b0 + b)) * CO + tb] = v;  // final v2
        }
        __syncthreads();
    }
}

extern "C" void kernel_launch(void* const* d_in, const int* in_sizes, int n_in,
                              void* d_out, int out_size) {
    (void)in_sizes; (void)n_in; (void)out_size;
    const float* x = (const float*)d_in[0];
    const float* W = (const float*)d_in[1];
    float* out = (float*)d_out;

    cudaFuncSetAttribute(caps_kernel,
                         cudaFuncAttributeMaxDynamicSharedMemorySize, SMEM_TOTAL);
    dim3 grid(GROUPS, NCAPS);
    caps_kernel<<<grid, NTHREADS, SMEM_TOTAL>>>(x, W, out);
}

// round 2
// speedup vs baseline: 1.4371x; 1.4371x over previous
#include <cuda_runtime.h>
#include <cuda_fp16.h>
#include <cstdint>

// CapsuleLayer dynamic routing, 3 rounds.
// x: [512, 1152, 8] fp32   W: [10, 1152, 8, 16] fp32   out: [10, 512, 16] fp32
//
// Block = (n, 4 batches). Phase 1: priors p[b][r][16] once into fp16 smem
// (PSTR=20 halves/row -> conflict-free 8B accesses), GEMM uses packed
// fma.rn.f32x2. Phase 2: routing with register-resident rows:
//   v0 = squash(mean_r p_r); rounds: a_r = p_r.w, softmax (shfl reductions),
//   S = sum e_r p_r accumulated in registers, reduced with a 16-shfl
//   split-exchange tree + per-b-group named barriers.
//   w = v0, then v0+v1 (logit updates are additive in p).

#define NCAPS 10
#define NB    512
#define NR    1152
#define CI    8
#define CO    16
#define BT    4
#define NTHREADS 384
#define GROUPS (NB / BT)      // 128
#define TPB   96              // threads per batch (3 warps)
#define RPT   (NR / NTHREADS) // 3
#define KPT   (NR / TPB)      // 12
#define PSTR  20              // halves per prior row (16 data + 4 pad)

// shared memory layout (bytes)
#define P_BYTES    (BT * NR * PSTR * 2)   // 184320 fp16 priors
#define SRED_OFF   P_BYTES
#define SRED_BYTES (BT * 3 * CO * 4)      // 768   per-warp S partials
#define WRED_OFF   (SRED_OFF + SRED_BYTES)
#define WRED_BYTES (BT * 8 * 4)           // 128   per-warp m/Z partials
#define VDOT_OFF   (WRED_OFF + WRED_BYTES)
#define VDOT_BYTES (BT * CO * 4)          // 256   routing weight vector
#define SMEM_TOTAL (VDOT_OFF + VDOT_BYTES)

struct __align__(8) H4 { __half2 a, b; };

__device__ __forceinline__ void fma2(unsigned long long& d,
                                     unsigned long long a,
                                     unsigned long long b) {
    asm("fma.rn.f32x2 %0, %1, %2, %0;" : "+l"(d) : "l"(a), "l"(b));
}
__device__ __forceinline__ unsigned long long pack2(float x) {
    unsigned long long r;
    asm("mov.b64 %0, {%1, %1};" : "=l"(r) : "f"(x));
    return r;
}
__device__ __forceinline__ float2 unpack2(unsigned long long v) {
    float2 f;
    asm("mov.b64 {%0, %1}, %2;" : "=f"(f.x), "=f"(f.y) : "l"(v));
    return f;
}
__device__ __forceinline__ void bar_group(int id) {
    asm volatile("bar.sync %0, %1;" :: "r"(id), "r"(TPB) : "memory");
}
__device__ __forceinline__ void load_row(const __half* pr, float f[CO]) {
    #pragma unroll
    for (int q = 0; q < 4; ++q) {
        const H4 u = *(const H4*)(pr + q * 4);
        const float2 f0 = __half22float2(u.a);
        const float2 f1 = __half22float2(u.b);
        f[q*4+0] = f0.x; f[q*4+1] = f0.y; f[q*4+2] = f1.x; f[q*4+3] = f1.y;
    }
}

// Split-exchange reduce of S[16] over 32 lanes: 16 shfl total. Even lanes end
// holding the full 32-lane sum of component comp(lane); they write it to sred.
__device__ __forceinline__ void reduce_s16(float S[CO], int lane,
                                           float* sred_warp) {
    const bool h16 = lane & 16;
    #pragma unroll
    for (int j = 0; j < 8; ++j) {
        const float snd = h16 ? S[j] : S[j + 8];
        const float kp  = h16 ? S[j + 8] : S[j];
        S[j] = kp + __shfl_xor_sync(0xffffffffu, snd, 16);
    }
    const bool h8 = lane & 8;
    #pragma unroll
    for (int j = 0; j < 4; ++j) {
        const float snd = h8 ? S[j] : S[j + 4];
        const float kp  = h8 ? S[j + 4] : S[j];
        S[j] = kp + __shfl_xor_sync(0xffffffffu, snd, 8);
    }
    const bool h4 = lane & 4;
    #pragma unroll
    for (int j = 0; j < 2; ++j) {
        const float snd = h4 ? S[j] : S[j + 2];
        const float kp  = h4 ? S[j + 2] : S[j];
        S[j] = kp + __shfl_xor_sync(0xffffffffu, snd, 4);
    }
    const bool h2 = lane & 2;
    {
        const float snd = h2 ? S[0] : S[1];
        const float kp  = h2 ? S[1] : S[0];
        S[0] = kp + __shfl_xor_sync(0xffffffffu, snd, 2);
    }
    S[0] += __shfl_xor_sync(0xffffffffu, S[0], 1);
    const int comp = ((lane >> 4) & 1) * 8 + ((lane >> 3) & 1) * 4 +
                     ((lane >> 2) & 1) * 2 + ((lane >> 1) & 1);
    if (!(lane & 1)) sred_warp[comp] = S[0];
}

__global__ void __launch_bounds__(NTHREADS, 1)
caps_kernel(const float* __restrict__ x,
            const float* __restrict__ W,
            float* __restrict__ out) {
    extern __shared__ char smem[];
    __half* p   = (__half*)smem;
    float* sred = (float*)(smem + SRED_OFF);
    float* wred = (float*)(smem + WRED_OFF);
    float* vdot = (float*)(smem + VDOT_OFF);

    const int n  = blockIdx.y;
    const int b0 = blockIdx.x * BT;
    const int t  = threadIdx.x;

    // ================= Phase 1: priors GEMM (packed f32x2 FMA) =============
    #pragma unroll
    for (int rr = 0; rr < RPT; ++rr) {
        const int r = t + rr * NTHREADS;
        float xv[BT][CI];
        #pragma unroll
        for (int b = 0; b < BT; ++b) {
            const float4* xp = (const float4*)(x + ((size_t)(b0 + b) * NR + r) * CI);
            const float4 x0 = xp[0], x1 = xp[1];
            xv[b][0]=x0.x; xv[b][1]=x0.y; xv[b][2]=x0.z; xv[b][3]=x0.w;
            xv[b][4]=x1.x; xv[b][5]=x1.y; xv[b][6]=x1.z; xv[b][7]=x1.w;
        }
        unsigned long long acc[BT][8];
        #pragma unroll
        for (int b = 0; b < BT; ++b)
            #pragma unroll
            for (int j = 0; j < 8; ++j) acc[b][j] = 0ull;

        const ulonglong2* wr =
            (const ulonglong2*)(W + ((size_t)n * NR + r) * (CI * CO));
        #pragma unroll
        for (int i = 0; i < CI; ++i) {
            const ulonglong2 wA = wr[i * 4 + 0];   // floats 0..3
            const ulonglong2 wB = wr[i * 4 + 1];   // floats 4..7
            const ulonglong2 wC = wr[i * 4 + 2];   // floats 8..11
            const ulonglong2 wD = wr[i * 4 + 3];   // floats 12..15
            #pragma unroll
            for (int b = 0; b < BT; ++b) {
                const unsigned long long xx = pack2(xv[b][i]);
                fma2(acc[b][0], xx, wA.x); fma2(acc[b][1], xx, wA.y);
                fma2(acc[b][2], xx, wB.x); fma2(acc[b][3], xx, wB.y);
                fma2(acc[b][4], xx, wC.x); fma2(acc[b][5], xx, wC.y);
                fma2(acc[b][6], xx, wD.x); fma2(acc[b][7], xx, wD.y);
            }
        }
        #pragma unroll
        for (int b = 0; b < BT; ++b) {
            __half* dst = p + (size_t)(b * NR + r) * PSTR;
            #pragma unroll
            for (int g = 0; g < 4; ++g) {
                const float2 f0 = unpack2(acc[b][2*g + 0]);
                const float2 f1 = unpack2(acc[b][2*g + 1]);
                H4 h;
                h.a = __floats2half2_rn(f0.x, f0.y);
                h.b = __floats2half2_rn(f1.x, f1.y);
                *(H4*)(dst + g * 4) = h;
            }
        }
    }
    __syncthreads();

    // ================= Phase 2: routing =================
    const int b    = t / TPB;      // 0..3
    const int tb   = t % TPB;      // 0..95
    const int lane = tb & 31;
    const int wl   = tb >> 5;      // warp within group 0..2
    const int bid  = b + 1;        // named barrier id
    const __half* pb = p + (size_t)b * NR * PSTR;
    float* sredb = sred + b * 3 * CO;
    float* wredb = wred + b * 8;
    float* vdotb = vdot + b * CO;

    // ---- v0 = squash(mean_r p_r) ----
    {
        float S[CO];
        #pragma unroll
        for (int o = 0; o < CO; ++o) S[o] = 0.f;
        #pragma unroll
        for (int k = 0; k < KPT; ++k) {
            float f[CO];
            load_row(pb + (size_t)(tb + k * TPB) * PSTR, f);
            #pragma unroll
            for (int o = 0; o < CO; ++o) S[o] += f[o];
        }
        reduce_s16(S, lane, sredb + wl * CO);
        bar_group(bid);
        if (tb < CO) {
            const float s = sredb[tb] + sredb[CO + tb] + sredb[2*CO + tb];
            const float v = s * (1.0f / NR);
            float sq = v * v;
            #pragma unroll
            for (int off = 8; off; off >>= 1)
                sq += __shfl_xor_sync(0xffffu, sq, off);
            const float coef = sq / ((1.f + sq) * sqrtf(sq));
            vdotb[tb] = v * coef;
        }
        bar_group(bid);
    }

    // ---- rounds 1 and 2 ----
    #pragma unroll
    for (int round = 0; round < 2; ++round) {
        float vd[CO];
        #pragma unroll
        for (int o = 0; o < CO; ++o) vd[o] = vdotb[o];

        float a[KPT];
        float mloc = -1e30f;
        #pragma unroll
        for (int k = 0; k < KPT; ++k) {
            float f[CO];
            load_row(pb + (size_t)(tb + k * TPB) * PSTR, f);
            float s = 0.f;
            #pragma unroll
            for (int o = 0; o < CO; ++o) s += f[o] * vd[o];
            a[k] = s;
            mloc = fmaxf(mloc, s);
        }
        #pragma unroll
        for (int off = 16; off; off >>= 1)
            mloc = fmaxf(mloc, __shfl_xor_sync(0xffffffffu, mloc, off));
        if (lane == 0) wredb[wl] = mloc;
        bar_group(bid);
        const float m = fmaxf(fmaxf(wredb[0], wredb[1]), wredb[2]);

        float zloc = 0.f;
        #pragma unroll
        for (int k = 0; k < KPT; ++k) {
            a[k] = __expf(a[k] - m);
            zloc += a[k];
        }
        #pragma unroll
        for (int off = 16; off; off >>= 1)
            zloc += __shfl_xor_sync(0xffffffffu, zloc, off);
        if (lane == 0) wredb[4 + wl] = zloc;
        bar_group(bid);
        const float Z = wredb[4] + wredb[5] + wredb[6];

        float S[CO];
        #pragma unroll
        for (int o = 0; o < CO; ++o) S[o] = 0.f;
        #pragma unroll
        for (int k = 0; k < KPT; ++k) {
            float f[CO];
            load_row(pb + (size_t)(tb + k * TPB) * PSTR, f);
            const float e = a[k];
            #pragma unroll
            for (int o = 0; o < CO; ++o) S[o] += e * f[o];
        }
        reduce_s16(S, lane, sredb + wl * CO);
        bar_group(bid);

        if (tb < CO) {
            const float s = sredb[tb] + sredb[CO + tb] + sredb[2*CO + tb];
            const float v = s / Z;
            float sq = v * v;
            #pragma unroll
            for (int off = 8; off; off >>= 1)
                sq += __shfl_xor_sync(0xffffu, sq, off);
            const float coef = sq / ((1.f + sq) * sqrtf(sq));
            const float res = v * coef;
            if (round == 0)
                vdotb[tb] += res;                       // w = v0 + v1
            else
                out[((size_t)n * NB + (b0 + b)) * CO + tb] = res;
        }
        bar_group(bid);
    }
}

extern "C" void kernel_launch(void* const* d_in, const int* in_sizes, int n_in,
                              void* d_out, int out_size) {
    (void)in_sizes; (void)n_in; (void)out_size;
    const float* x = (const float*)d_in[0];
    const float* W = (const float*)d_in[1];
    float* out = (float*)d_out;

    cudaFuncSetAttribute(caps_kernel,
                         cudaFuncAttributeMaxDynamicSharedMemorySize, SMEM_TOTAL);
    dim3 grid(GROUPS, NCAPS);
    caps_kernel<<<grid, NTHREADS, SMEM_TOTAL>>>(x, W, out);
}

// round 3
// speedup vs baseline: 2.3990x; 1.6694x over previous
#include <cuda_runtime.h>
#include <cuda_fp16.h>
#include <cstdint>

// CapsuleLayer dynamic routing, 3 rounds.
// x: [512, 1152, 8] fp32   W: [10, 1152, 8, 16] fp32   out: [10, 512, 16] fp32
//
// Block = (n, 4 batches), 768 threads, 85-reg cap (24 warps/SM).
// Phase 1 (priors GEMM): warp-coalesced W access. Lane = (row-of-quad, o-pair):
//   each LDG.64 of W touches ~4 cache lines for the whole warp (vs 32 in the
//   thread-private-row layout). One fma.rn.f32x2 per (i, b). Priors -> fp16
//   smem, PSTR=20 halves/row (conflict-free 8B routing loads).
// Phase 2 (routing): 4 groups x 192 threads, 6 rows/thread.
//   v0 = squash(mean_r p_r); rounds: a = p.w, softmax (shfl + named barriers),
//   S = sum e_r p_r in registers, 16-shfl split-exchange reduce.
//   w = v0, then v0+v1 (logit updates additive in p).

#define NCAPS 10
#define NB    512
#define NR    1152
#define CI    8
#define CO    16
#define BT    4
#define NTHREADS 768
#define GROUPS (NB / BT)      // 128
#define TPB   192             // threads per batch group (6 warps)
#define WPG   6               // warps per group
#define KPT   (NR / TPB)      // 6 rows per thread in routing
#define NWARP (NTHREADS / 32) // 24
#define QITER (NR / (4 * NWARP)) // 12 row-quads per warp in phase 1
#define PSTR  20              // halves per prior row (16 data + 4 pad)

// shared memory layout (bytes)
#define P_BYTES    (BT * NR * PSTR * 2)   // 184320 fp16 priors
#define SRED_OFF   P_BYTES
#define SRED_BYTES (BT * WPG * CO * 4)    // 1536  per-warp S partials
#define WRED_OFF   (SRED_OFF + SRED_BYTES)
#define WRED_BYTES (BT * 2 * WPG * 4)     // 192   per-warp m/Z partials
#define VDOT_OFF   (WRED_OFF + WRED_BYTES)
#define VDOT_BYTES (BT * CO * 4)          // 256   routing weight vector
#define SMEM_TOTAL (VDOT_OFF + VDOT_BYTES)

struct __align__(8) H4 { __half2 a, b; };

__device__ __forceinline__ void fma2(unsigned long long& d,
                                     unsigned long long a,
                                     unsigned long long b) {
    asm("fma.rn.f32x2 %0, %1, %2, %0;" : "+l"(d) : "l"(a), "l"(b));
}
__device__ __forceinline__ unsigned long long pack2(float x) {
    unsigned long long r;
    asm("mov.b64 %0, {%1, %1};" : "=l"(r) : "f"(x));
    return r;
}
__device__ __forceinline__ float2 unpack2(unsigned long long v) {
    float2 f;
    asm("mov.b64 {%0, %1}, %2;" : "=f"(f.x), "=f"(f.y) : "l"(v));
    return f;
}
__device__ __forceinline__ void bar_group(int id) {
    asm volatile("bar.sync %0, %1;" :: "r"(id), "r"(TPB) : "memory");
}
__device__ __forceinline__ void load_row(const __half* pr, float f[CO]) {
    #pragma unroll
    for (int q = 0; q < 4; ++q) {
        const H4 u = *(const H4*)(pr + q * 4);
        const float2 f0 = __half22float2(u.a);
        const float2 f1 = __half22float2(u.b);
        f[q*4+0] = f0.x; f[q*4+1] = f0.y; f[q*4+2] = f1.x; f[q*4+3] = f1.y;
    }
}

// Split-exchange reduce of S[16] over 32 lanes: 16 shfl total. Even lanes end
// holding the full 32-lane sum of component comp(lane); write to sred_warp.
__device__ __forceinline__ void reduce_s16(float S[CO], int lane,
                                           float* sred_warp) {
    const bool h16 = lane & 16;
    #pragma unroll
    for (int j = 0; j < 8; ++j) {
        const float snd = h16 ? S[j] : S[j + 8];
        const float kp  = h16 ? S[j + 8] : S[j];
        S[j] = kp + __shfl_xor_sync(0xffffffffu, snd, 16);
    }
    const bool h8 = lane & 8;
    #pragma unroll
    for (int j = 0; j < 4; ++j) {
        const float snd = h8 ? S[j] : S[j + 4];
        const float kp  = h8 ? S[j + 4] : S[j];
        S[j] = kp + __shfl_xor_sync(0xffffffffu, snd, 8);
    }
    const bool h4 = lane & 4;
    #pragma unroll
    for (int j = 0; j < 2; ++j) {
        const float snd = h4 ? S[j] : S[j + 2];
        const float kp  = h4 ? S[j + 2] : S[j];
        S[j] = kp + __shfl_xor_sync(0xffffffffu, snd, 4);
    }
    const bool h2 = lane & 2;
    {
        const float snd = h2 ? S[0] : S[1];
        const float kp  = h2 ? S[1] : S[0];
        S[0] = kp + __shfl_xor_sync(0xffffffffu, snd, 2);
    }
    S[0] += __shfl_xor_sync(0xffffffffu, S[0], 1);
    const int comp = ((lane >> 4) & 1) * 8 + ((lane >> 3) & 1) * 4 +
                     ((lane >> 2) & 1) * 2 + ((lane >> 1) & 1);
    if (!(lane & 1)) sred_warp[comp] = S[0];
}

__global__ void __launch_bounds__(NTHREADS, 1)
caps_kernel(const float* __restrict__ x,
            const float* __restrict__ W,
            float* __restrict__ out) {
    extern __shared__ char smem[];
    __half* p   = (__half*)smem;
    float* sred = (float*)(smem + SRED_OFF);
    float* wred = (float*)(smem + WRED_OFF);
    float* vdot = (float*)(smem + VDOT_OFF);

    const int n  = blockIdx.y;
    const int b0 = blockIdx.x * BT;
    const int t  = threadIdx.x;
    const int wid  = t >> 5;
    const int lane = t & 31;

    // ======== Phase 1: priors GEMM, warp-coalesced W ========
    // lane -> (rl, op): row-in-quad 0..3, o-pair 0..7
    {
        const int rl = lane >> 3;
        const int op = lane & 7;
        #pragma unroll 2
        for (int j = 0; j < QITER; ++j) {
            const int r = (wid + j * NWARP) * 4 + rl;
            // x rows (broadcast among the 8 lanes sharing a row)
            float xv[BT][CI];
            #pragma unroll
            for (int b = 0; b < BT; ++b) {
                const float4* xp =
                    (const float4*)(x + ((size_t)(b0 + b) * NR + r) * CI);
                const float4 x0 = xp[0], x1 = xp[1];
                xv[b][0]=x0.x; xv[b][1]=x0.y; xv[b][2]=x0.z; xv[b][3]=x0.w;
                xv[b][4]=x1.x; xv[b][5]=x1.y; xv[b][6]=x1.z; xv[b][7]=x1.w;
            }
            // W o-pair column: ull index (n*NR+r)*64 + i*8 + op
            const unsigned long long* wr =
                (const unsigned long long*)W + ((size_t)n * NR + r) * 64 + op;
            unsigned long long acc[BT];
            #pragma unroll
            for (int b = 0; b < BT; ++b) acc[b] = 0ull;
            #pragma unroll
            for (int i = 0; i < CI; ++i) {
                const unsigned long long w = wr[i * 8];
                #pragma unroll
                for (int b = 0; b < BT; ++b)
                    fma2(acc[b], pack2(xv[b][i]), w);
            }
            #pragma unroll
            for (int b = 0; b < BT; ++b) {
                const float2 f = unpack2(acc[b]);
                *(__half2*)(p + (size_t)(b * NR + r) * PSTR + op * 2) =
                    __floats2half2_rn(f.x, f.y);
            }
        }
    }
    __syncthreads();

    // ======== Phase 2: routing ========
    const int b    = t / TPB;      // 0..3
    const int tb   = t % TPB;      // 0..191
    const int wl   = (tb >> 5);    // warp in group 0..5
    const int bid  = b + 1;        // named barrier id
    const __half* pb = p + (size_t)b * NR * PSTR;
    float* sredb = sred + b * WPG * CO;
    float* wredb = wred + b * 2 * WPG;
    float* vdotb = vdot + b * CO;

    // ---- v0 = squash(mean_r p_r) ----
    {
        float S[CO];
        #pragma unroll
        for (int o = 0; o < CO; ++o) S[o] = 0.f;
        #pragma unroll
        for (int k = 0; k < KPT; ++k) {
            float f[CO];
            load_row(pb + (size_t)(tb + k * TPB) * PSTR, f);
            #pragma unroll
            for (int o = 0; o < CO; ++o) S[o] += f[o];
        }
        reduce_s16(S, lane, sredb + wl * CO);
        bar_group(bid);
        if (tb < CO) {
            float s = 0.f;
            #pragma unroll
            for (int w = 0; w < WPG; ++w) s += sredb[w * CO + tb];
            const float v = s * (1.0f / NR);
            float sq = v * v;
            #pragma unroll
            for (int off = 8; off; off >>= 1)
                sq += __shfl_xor_sync(0xffffu, sq, off);
            const float coef = sq / ((1.f + sq) * sqrtf(sq));
            vdotb[tb] = v * coef;
        }
        bar_group(bid);
    }

    // ---- rounds 1 and 2 ----
    #pragma unroll
    for (int round = 0; round < 2; ++round) {
        float vd[CO];
        #pragma unroll
        for (int o = 0; o < CO; ++o) vd[o] = vdotb[o];

        float a[KPT];
        float mloc = -1e30f;
        #pragma unroll
        for (int k = 0; k < KPT; ++k) {
            float f[CO];
            load_row(pb + (size_t)(tb + k * TPB) * PSTR, f);
            float s = 0.f;
            #pragma unroll
            for (int o = 0; o < CO; ++o) s += f[o] * vd[o];
            a[k] = s;
            mloc = fmaxf(mloc, s);
        }
        #pragma unroll
        for (int off = 16; off; off >>= 1)
            mloc = fmaxf(mloc, __shfl_xor_sync(0xffffffffu, mloc, off));
        if (lane == 0) wredb[wl] = mloc;
        bar_group(bid);
        float m = wredb[0];
        #pragma unroll
        for (int w = 1; w < WPG; ++w) m = fmaxf(m, wredb[w]);

        float zloc = 0.f;
        #pragma unroll
        for (int k = 0; k < KPT; ++k) {
            a[k] = __expf(a[k] - m);
            zloc += a[k];
        }
        #pragma unroll
        for (int off = 16; off; off >>= 1)
            zloc += __shfl_xor_sync(0xffffffffu, zloc, off);
        if (lane == 0) wredb[WPG + wl] = zloc;
        bar_group(bid);
        float Z = wredb[WPG];
        #pragma unroll
        for (int w = 1; w < WPG; ++w) Z += wredb[WPG + w];

        float S[CO];
        #pragma unroll
        for (int o = 0; o < CO; ++o) S[o] = 0.f;
        #pragma unroll
        for (int k = 0; k < KPT; ++k) {
            float f[CO];
            load_row(pb + (size_t)(tb + k * TPB) * PSTR, f);
            const float e = a[k];
            #pragma unroll
            for (int o = 0; o < CO; ++o) S[o] += e * f[o];
        }
        reduce_s16(S, lane, sredb + wl * CO);
        bar_group(bid);

        if (tb < CO) {
            float s = 0.f;
            #pragma unroll
            for (int w = 0; w < WPG; ++w) s += sredb[w * CO + tb];
            const float v = s / Z;
            float sq = v * v;
            #pragma unroll
            for (int off = 8; off; off >>= 1)
                sq += __shfl_xor_sync(0xffffu, sq, off);
            const float coef = sq / ((1.f + sq) * sqrtf(sq));
            const float res = v * coef;
            if (round == 0)
                vdotb[tb] += res;                       // w = v0 + v1
            else
                out[((size_t)n * NB + (b0 + b)) * CO + tb] = res;
        }
        bar_group(bid);
    }
}

extern "C" void kernel_launch(void* const* d_in, const int* in_sizes, int n_in,
                              void* d_out, int out_size) {
    (void)in_sizes; (void)n_in; (void)out_size;
    const float* x = (const float*)d_in[0];
    const float* W = (const float*)d_in[1];
    float* out = (float*)d_out;

    cudaFuncSetAttribute(caps_kernel,
                         cudaFuncAttributeMaxDynamicSharedMemorySize, SMEM_TOTAL);
    dim3 grid(GROUPS, NCAPS);
    caps_kernel<<<grid, NTHREADS, SMEM_TOTAL>>>(x, W, out);
}